// round 5
// baseline (speedup 1.0000x reference)
#include <cuda_runtime.h>

#define B_DIM 128
#define N_DIM 8192
#define HW    49
#define ROWQ  13               // float4 quads per row window (52 floats)
#define ROW_STRIDE_Q4 100352   // 8192*49/4 : float4 stride between rows of x

typedef unsigned long long u64;
typedef unsigned int u32;

__device__ __forceinline__ u64 pk2(float lo, float hi) {
    u64 r; asm("mov.b64 %0, {%1,%2};" : "=l"(r) : "f"(lo), "f"(hi)); return r;
}
__device__ __forceinline__ void upk2(u64 v, float& lo, float& hi) {
    asm("mov.b64 {%0,%1}, %2;" : "=f"(lo), "=f"(hi) : "l"(v));
}
__device__ __forceinline__ u64 fma2(u64 a, u64 b, u64 c) {
    u64 d; asm("fma.rn.f32x2 %0, %1, %2, %3;" : "=l"(d) : "l"(a), "l"(b), "l"(c)); return d;
}
__device__ __forceinline__ u64 add2(u64 a, u64 b) {
    u64 d; asm("add.rn.f32x2 %0, %1, %2;" : "=l"(d) : "l"(a), "l"(b)); return d;
}
__device__ __forceinline__ float ex2f(float x) {
    float y; asm("ex2.approx.ftz.f32 %0, %1;" : "=f"(y) : "f"(x)); return y;
}
// result = p * 2^i, i encoded in low mantissa bits of magic-rounded r; exact bit add.
__device__ __forceinline__ float scale_exp(float p, float r) {
    return __int_as_float(__float_as_int(p) + (__float_as_int(r) << 23));
}

__global__ __launch_bounds__(128, 7) void rsca_kernel(
    const float* __restrict__ x, const float* __restrict__ y,
    const float* __restrict__ swq, const float* __restrict__ swk,
    const float* __restrict__ swv, const float* __restrict__ sbq,
    const float* __restrict__ sbk, const float* __restrict__ sbv,
    const float* __restrict__ swo, const float* __restrict__ sbo,
    float* __restrict__ out)
{
    const int n = blockIdx.x;
    const int i = threadIdx.x;

    __shared__ float4 xs[B_DIM * ROWQ];   // 26624 B transposed x window
    __shared__ float4 kv[B_DIM];          // {kx, ky, vx, vy}
    __shared__ float4 wred[4];

    const float wq = *swq, wk = *swk, wv = *swv;
    const float bq = *sbq, bk = *sbk, bv = *sbv;
    const float wo = *swo, bo = *sbo;

    // ---- Phase 1: cooperative coalesced load of x window into smem ----
    const int a = n & 3;
    const size_t baseq = ((size_t)n * HW - a) >> 2;       // float4 offset, exact
    const float4* g4 = (const float4*)x + baseq;

    #pragma unroll
    for (int t = 0; t < ROWQ; ++t) {
        int idx = i + t * B_DIM;          // 0..1663 row-major (r, q)
        int r = idx / ROWQ, q = idx - r * ROWQ;
        xs[idx] = g4[(size_t)r * ROW_STRIDE_Q4 + q];
    }
    __syncthreads();

    // ---- Phase 2: per-thread row reduce from smem (a-corrections) ----
    // Quads 1..12 are consumed by the pair loop; quad 0 seeded; NO re-add of quad 12.
    float4 q0 = xs[i * ROWQ + 0];
    float4 q12 = xs[i * ROWQ + 12];
    float s0 = q0.x + q0.y, s1 = q0.z + q0.w, s2 = 0.f, s3 = 0.f;
    #pragma unroll
    for (int t = 1; t < 12; t += 2) {
        float4 u = xs[i * ROWQ + t];
        float4 w = xs[i * ROWQ + t + 1];
        s0 += u.x; s1 += u.y; s2 += u.z; s3 += u.w;
        s0 += w.x; s1 += w.y; s2 += w.z; s3 += w.w;
    }
    float sum = (s0 + s1) + (s2 + s3);    // w0..w51 each exactly once
    // valid window = [a, a+48]; remove the 3 invalid of the 52 loaded
    if (a >= 1) sum -= q0.x;  else sum -= q12.y;   // w0  vs w49
    if (a >= 2) sum -= q0.y;  else sum -= q12.z;   // w1  vs w50
    if (a >= 3) sum -= q0.z;  else sum -= q12.w;   // w2  vs w51

    const float ax = sum * (1.0f / 49.0f);
    const float ay = y[(size_t)i * N_DIM + (size_t)n];

    // ---- projections (k pre-scaled by log2 e) ----
    const float L2E = 1.4426950408889634f;
    const float qx = fmaf(ax, wq, bq);
    const float qy = fmaf(ay, wq, bq);
    const float kx = fmaf(ax, wk, bk) * L2E;
    const float ky = fmaf(ay, wk, bk) * L2E;
    const float vx = fmaf(ax, wv, bv);
    const float vy = fmaf(ay, wv, bv);

    kv[i] = make_float4(kx, ky, vx, vy);

    // ---- block min/max of kx, ky (analytic per-row softmax max) ----
    float kxmx = kx, kxmn = kx, kymx = ky, kymn = ky;
    #pragma unroll
    for (int off = 16; off; off >>= 1) {
        kxmx = fmaxf(kxmx, __shfl_xor_sync(0xFFFFFFFFu, kxmx, off));
        kxmn = fminf(kxmn, __shfl_xor_sync(0xFFFFFFFFu, kxmn, off));
        kymx = fmaxf(kymx, __shfl_xor_sync(0xFFFFFFFFu, kymx, off));
        kymn = fminf(kymn, __shfl_xor_sync(0xFFFFFFFFu, kymn, off));
    }
    if ((i & 31) == 0) wred[i >> 5] = make_float4(kxmx, kxmn, kymx, kymn);
    __syncthreads();
    {
        float4 r0 = wred[0], r1 = wred[1], r2 = wred[2], r3 = wred[3];
        kxmx = fmaxf(fmaxf(r0.x, r1.x), fmaxf(r2.x, r3.x));
        kxmn = fminf(fminf(r0.y, r1.y), fminf(r2.y, r3.y));
        kymx = fmaxf(fmaxf(r0.z, r1.z), fmaxf(r2.z, r3.z));
        kymn = fminf(fminf(r0.w, r1.w), fminf(r2.w, r3.w));
    }

    const float nm1 = -((qx >= 0.f) ? qx * kxmx : qx * kxmn);  // self_x : qx,kx
    const float nm2 = -((qy >= 0.f) ? qy * kymx : qy * kymn);  // self_y : qy,ky
    const float nm3 = -((qx >= 0.f) ? qx * kymx : qx * kymn);  // cross_x: qx,ky
    const float nm4 = -((qy >= 0.f) ? qy * kxmx : qy * kxmn);  // cross_y: qy,kx

    // packed constants
    const u64 qp12 = pk2(qx, qy);      // lanes (s1, s2)
    const u64 qp43 = pk2(qy, qx);      // lanes (s4, s3)
    const u64 nmp12 = pk2(nm1, nm2);
    const u64 nmp43 = pk2(nm4, nm3);
    const u64 MAG2  = pk2(12582912.0f, 12582912.0f);   // 1.5 * 2^23
    const u64 NMAG2 = pk2(-12582912.0f, -12582912.0f);
    const u64 NEG1  = pk2(-1.0f, -1.0f);
    const u64 C4 = pk2(0.009618129f, 0.009618129f);
    const u64 C3 = pk2(0.055504109f, 0.055504109f);
    const u64 C2 = pk2(0.240226507f, 0.240226507f);
    const u64 C1 = pk2(0.693147181f, 0.693147181f);
    const u64 C0 = pk2(1.0f, 1.0f);

    // ---- fused 4-combo attention: 2 exps on MUFU, 2 on FMA-pipe packed poly ----
    u64 d12 = 0, n12 = 0, d43 = 0, n43 = 0;

    #pragma unroll 4
    for (int j = 0; j < B_DIM; ++j) {
        const float4 p = kv[j];            // {kx, ky, vx, vy} (warp-uniform)
        const u64 kp = pk2(p.x, p.y);
        const u64 vp = pk2(p.z, p.w);

        // scores
        const u64 sc12 = fma2(qp12, kp, nmp12);    // (s1, s2), both <= 0
        const u64 sc43 = fma2(qp43, kp, nmp43);    // (s4, s3), both <= 0

        // MUFU path for combos 1,2
        float t1, t2; upk2(sc12, t1, t2);
        const float e1 = ex2f(t1);
        const float e2 = ex2f(t2);

        // packed poly exp2 for combos 4,3
        float t4, t3; upk2(sc43, t4, t3);
        t4 = fmaxf(t4, -120.0f);
        t3 = fmaxf(t3, -120.0f);
        const u64 t43 = pk2(t4, t3);
        const u64 r43 = add2(t43, MAG2);           // round-to-nearest int capture
        const u64 i43 = add2(r43, NMAG2);          // integer part (exact)
        const u64 f43 = fma2(NEG1, i43, t43);      // frac in [-0.5, 0.5] (exact)
        u64 pl = fma2(C4, f43, C3);
        pl = fma2(pl, f43, C2);
        pl = fma2(pl, f43, C1);
        pl = fma2(pl, f43, C0);
        float plo, phi, rlo, rhi;
        upk2(pl, plo, phi); upk2(r43, rlo, rhi);
        const float e4 = scale_exp(plo, rlo);
        const float e3 = scale_exp(phi, rhi);

        // packed accumulation
        const u64 e12 = pk2(e1, e2);
        const u64 e43 = pk2(e4, e3);
        d12 = add2(d12, e12); n12 = fma2(e12, vp, n12);   // n1+=e1*vx, n2+=e2*vy
        d43 = add2(d43, e43); n43 = fma2(e43, vp, n43);   // n4+=e4*vx, n3+=e3*vy
    }

    float nn1, nn2, dd1, dd2, nn4, nn3, dd4, dd3;
    upk2(n12, nn1, nn2); upk2(d12, dd1, dd2);
    upk2(n43, nn4, nn3); upk2(d43, dd4, dd3);

    const float osx = __fdividef(nn1, dd1);
    const float osy = __fdividef(nn2, dd2);
    const float ocx = __fdividef(nn3, dd3);
    const float ocy = __fdividef(nn4, dd4);

    const float ox = fmaf(wo, osx + ocx, ax + 2.0f * bo);
    const float oy = fmaf(wo, osy + ocy, ay + 2.0f * bo);

    out[(size_t)i * (2 * N_DIM) + (size_t)n]         = ox;
    out[(size_t)i * (2 * N_DIM) + N_DIM + (size_t)n] = oy;
}

extern "C" void kernel_launch(void* const* d_in, const int* in_sizes, int n_in,
                              void* d_out, int out_size) {
    const float* x   = (const float*)d_in[0];
    const float* y   = (const float*)d_in[1];
    const float* swq = (const float*)d_in[2];
    const float* swk = (const float*)d_in[3];
    const float* swv = (const float*)d_in[4];
    const float* sbq = (const float*)d_in[5];
    const float* sbk = (const float*)d_in[6];
    const float* sbv = (const float*)d_in[7];
    const float* swo = (const float*)d_in[8];
    const float* sbo = (const float*)d_in[9];
    float* out = (float*)d_out;

    rsca_kernel<<<N_DIM, B_DIM>>>(x, y, swq, swk, swv, sbq, sbk, sbv, swo, sbo, out);
}

// round 6
// speedup vs baseline: 1.2693x; 1.2693x over previous
#include <cuda_runtime.h>

#define B_DIM 128
#define N_DIM 8192
#define HW    49
#define ROWQ  13               // float4 quads per row window (52 floats)
#define ROW_STRIDE_Q4 100352   // 8192*49/4 : float4 stride between rows of x

typedef unsigned long long u64;
typedef unsigned int u32;

__device__ __forceinline__ u64 pk2(float lo, float hi) {
    u64 r; asm("mov.b64 %0, {%1,%2};" : "=l"(r) : "f"(lo), "f"(hi)); return r;
}
__device__ __forceinline__ void upk2(u64 v, float& lo, float& hi) {
    asm("mov.b64 {%0,%1}, %2;" : "=f"(lo), "=f"(hi) : "l"(v));
}
__device__ __forceinline__ u64 fma2(u64 a, u64 b, u64 c) {
    u64 d; asm("fma.rn.f32x2 %0, %1, %2, %3;" : "=l"(d) : "l"(a), "l"(b), "l"(c)); return d;
}
__device__ __forceinline__ u64 add2(u64 a, u64 b) {
    u64 d; asm("add.rn.f32x2 %0, %1, %2;" : "=l"(d) : "l"(a), "l"(b)); return d;
}
// f32x2 arg -> f16x2 -> 2^t for both halves: ONE MUFU instruction for two exps
__device__ __forceinline__ u32 ex2h2(u64 a) {
    float lo, hi; upk2(a, lo, hi);
    u32 h; asm("cvt.rn.f16x2.f32 %0, %1, %2;" : "=r"(h) : "f"(hi), "f"(lo));
    u32 e; asm("ex2.approx.f16x2 %0, %1;" : "=r"(e) : "r"(h));
    return e;
}
// f16x2 -> f32x2 scaled by 2^-112 (EXACT, incl. f16 subnormals); scale cancels in n/d
__device__ __forceinline__ u64 h2f2s(u32 e) {
    u32 lo = (e << 13) & 0x0FFFE000u;
    u32 hi = (e >> 3)  & 0x0FFFE000u;
    return pk2(__uint_as_float(lo), __uint_as_float(hi));
}

__global__ __launch_bounds__(128, 10) void rsca_kernel(
    const float* __restrict__ x, const float* __restrict__ y,
    const float* __restrict__ swq, const float* __restrict__ swk,
    const float* __restrict__ swv, const float* __restrict__ sbq,
    const float* __restrict__ sbk, const float* __restrict__ sbv,
    const float* __restrict__ swo, const float* __restrict__ sbo,
    float* __restrict__ out)
{
    const int n = blockIdx.x;
    const int i = threadIdx.x;

    __shared__ float4 xs[B_DIM * ROWQ];   // 26624 B transposed x window
    __shared__ float4 kv[B_DIM];          // {kx, ky, vx, vy}
    __shared__ float4 wred[4];

    const float wq = *swq, wk = *swk, wv = *swv;
    const float bq = *sbq, bk = *sbk, bv = *sbv;
    const float wo = *swo, bo = *sbo;

    // ---- Phase 1: cooperative coalesced load of x window into smem ----
    const int a = n & 3;
    const size_t baseq = ((size_t)n * HW - a) >> 2;       // float4 offset, exact
    const float4* g4 = (const float4*)x + baseq;

    #pragma unroll
    for (int t = 0; t < ROWQ; ++t) {
        int idx = i + t * B_DIM;          // 0..1663 row-major (r, q)
        int r = idx / ROWQ, q = idx - r * ROWQ;
        xs[idx] = g4[(size_t)r * ROW_STRIDE_Q4 + q];
    }
    __syncthreads();

    // ---- Phase 2: per-thread row reduce (w0..w51 each EXACTLY once) ----
    float4 q0 = xs[i * ROWQ + 0];
    float4 q12 = xs[i * ROWQ + 12];
    float s0 = q0.x + q0.y, s1 = q0.z + q0.w, s2 = 0.f, s3 = 0.f;
    #pragma unroll
    for (int t = 1; t < 12; t += 2) {
        float4 u = xs[i * ROWQ + t];
        float4 w = xs[i * ROWQ + t + 1];
        s0 += u.x; s1 += u.y; s2 += u.z; s3 += u.w;
        s0 += w.x; s1 += w.y; s2 += w.z; s3 += w.w;
    }
    float sum = (s0 + s1) + (s2 + s3);
    // valid window = [a, a+48]; remove the 3 invalid of the 52 loaded
    if (a >= 1) sum -= q0.x;  else sum -= q12.y;   // w0  vs w49
    if (a >= 2) sum -= q0.y;  else sum -= q12.z;   // w1  vs w50
    if (a >= 3) sum -= q0.z;  else sum -= q12.w;   // w2  vs w51

    const float ax = sum * (1.0f / 49.0f);
    const float ay = y[(size_t)i * N_DIM + (size_t)n];

    // ---- projections (k pre-scaled by log2 e) ----
    const float L2E = 1.4426950408889634f;
    const float qx = fmaf(ax, wq, bq);
    const float qy = fmaf(ay, wq, bq);
    const float kx = fmaf(ax, wk, bk) * L2E;
    const float ky = fmaf(ay, wk, bk) * L2E;
    const float vx = fmaf(ax, wv, bv);
    const float vy = fmaf(ay, wv, bv);

    kv[i] = make_float4(kx, ky, vx, vy);

    // ---- block min/max of kx, ky (analytic per-row softmax max) ----
    float kxmx = kx, kxmn = kx, kymx = ky, kymn = ky;
    #pragma unroll
    for (int off = 16; off; off >>= 1) {
        kxmx = fmaxf(kxmx, __shfl_xor_sync(0xFFFFFFFFu, kxmx, off));
        kxmn = fminf(kxmn, __shfl_xor_sync(0xFFFFFFFFu, kxmn, off));
        kymx = fmaxf(kymx, __shfl_xor_sync(0xFFFFFFFFu, kymx, off));
        kymn = fminf(kymn, __shfl_xor_sync(0xFFFFFFFFu, kymn, off));
    }
    if ((i & 31) == 0) wred[i >> 5] = make_float4(kxmx, kxmn, kymx, kymn);
    __syncthreads();
    {
        float4 r0 = wred[0], r1 = wred[1], r2 = wred[2], r3 = wred[3];
        kxmx = fmaxf(fmaxf(r0.x, r1.x), fmaxf(r2.x, r3.x));
        kxmn = fminf(fminf(r0.y, r1.y), fminf(r2.y, r3.y));
        kymx = fmaxf(fmaxf(r0.z, r1.z), fmaxf(r2.z, r3.z));
        kymn = fminf(fminf(r0.w, r1.w), fminf(r2.w, r3.w));
    }

    const float nm1 = -((qx >= 0.f) ? qx * kxmx : qx * kxmn);  // self_x : qx,kx
    const float nm2 = -((qy >= 0.f) ? qy * kymx : qy * kymn);  // self_y : qy,ky
    const float nm3 = -((qx >= 0.f) ? qx * kymx : qx * kymn);  // cross_x: qx,ky
    const float nm4 = -((qy >= 0.f) ? qy * kxmx : qy * kxmn);  // cross_y: qy,kx

    const u64 qp12 = pk2(qx, qy);      // lanes (s1, s2)
    const u64 qp43 = pk2(qy, qx);      // lanes (s4, s3)
    const u64 nmp12 = pk2(nm1, nm2);
    const u64 nmp43 = pk2(nm4, nm3);

    // ---- fused 4-combo attention: 2 f16x2 MUFU exps per j (= 4 exps) ----
    u64 d12 = 0, n12 = 0, d43 = 0, n43 = 0;

    #pragma unroll 8
    for (int j = 0; j < B_DIM; ++j) {
        const float4 p = kv[j];            // {kx, ky, vx, vy} (warp-uniform)
        const u64 kp = pk2(p.x, p.y);
        const u64 vp = pk2(p.z, p.w);

        const u64 sc12 = fma2(qp12, kp, nmp12);    // (s1, s2), <= 0
        const u64 sc43 = fma2(qp43, kp, nmp43);    // (s4, s3), <= 0

        const u32 e12 = ex2h2(sc12);               // 1 MUFU: e1, e2
        const u32 e43 = ex2h2(sc43);               // 1 MUFU: e4, e3

        const u64 f12 = h2f2s(e12);                // f32x2, x 2^-112 exact
        const u64 f43 = h2f2s(e43);

        d12 = add2(d12, f12); n12 = fma2(f12, vp, n12);   // n1+=e1*vx, n2+=e2*vy
        d43 = add2(d43, f43); n43 = fma2(f43, vp, n43);   // n4+=e4*vx, n3+=e3*vy
    }

    float nn1, nn2, dd1, dd2, nn4, nn3, dd4, dd3;
    upk2(n12, nn1, nn2); upk2(d12, dd1, dd2);
    upk2(n43, nn4, nn3); upk2(d43, dd4, dd3);

    const float osx = __fdividef(nn1, dd1);   // 2^-112 scale cancels
    const float osy = __fdividef(nn2, dd2);
    const float ocx = __fdividef(nn3, dd3);
    const float ocy = __fdividef(nn4, dd4);

    const float ox = fmaf(wo, osx + ocx, ax + 2.0f * bo);
    const float oy = fmaf(wo, osy + ocy, ay + 2.0f * bo);

    out[(size_t)i * (2 * N_DIM) + (size_t)n]         = ox;
    out[(size_t)i * (2 * N_DIM) + N_DIM + (size_t)n] = oy;
}

extern "C" void kernel_launch(void* const* d_in, const int* in_sizes, int n_in,
                              void* d_out, int out_size) {
    const float* x   = (const float*)d_in[0];
    const float* y   = (const float*)d_in[1];
    const float* swq = (const float*)d_in[2];
    const float* swk = (const float*)d_in[3];
    const float* swv = (const float*)d_in[4];
    const float* sbq = (const float*)d_in[5];
    const float* sbk = (const float*)d_in[6];
    const float* sbv = (const float*)d_in[7];
    const float* swo = (const float*)d_in[8];
    const float* sbo = (const float*)d_in[9];
    float* out = (float*)d_out;

    rsca_kernel<<<N_DIM, B_DIM>>>(x, y, swq, swk, swv, sbq, sbk, sbv, swo, sbo, out);
}

// round 8
// speedup vs baseline: 1.3496x; 1.0632x over previous
#include <cuda_runtime.h>

#define B_DIM 128
#define N_DIM 8192
#define HW    49
#define ROWQ  13               // float4 quads per row window (52 floats)
#define HALF_QUADS (64 * ROWQ) // 832 quads staged per pass
#define ROW_STRIDE_Q4 100352   // 8192*49/4 : float4 stride between rows of x

typedef unsigned long long u64;
typedef unsigned int u32;

__device__ __forceinline__ u64 pk2(float lo, float hi) {
    u64 r; asm("mov.b64 %0, {%1,%2};" : "=l"(r) : "f"(lo), "f"(hi)); return r;
}
__device__ __forceinline__ void upk2(u64 v, float& lo, float& hi) {
    asm("mov.b64 {%0,%1}, %2;" : "=f"(lo), "=f"(hi) : "l"(v));
}
__device__ __forceinline__ u64 fma2(u64 a, u64 b, u64 c) {
    u64 d; asm("fma.rn.f32x2 %0, %1, %2, %3;" : "=l"(d) : "l"(a), "l"(b), "l"(c)); return d;
}
__device__ __forceinline__ u64 add2(u64 a, u64 b) {
    u64 d; asm("add.rn.f32x2 %0, %1, %2;" : "=l"(d) : "l"(a), "l"(b)); return d;
}
// f32x2 arg -> f16x2 -> 2^t for both halves: ONE MUFU instruction for two exps
__device__ __forceinline__ u32 ex2h2(u64 a) {
    float lo, hi; upk2(a, lo, hi);
    u32 h; asm("cvt.rn.f16x2.f32 %0, %1, %2;" : "=r"(h) : "f"(hi), "f"(lo));
    u32 e; asm("ex2.approx.f16x2 %0, %1;" : "=r"(e) : "r"(h));
    return e;
}
// f16x2 -> f32x2 scaled 2^-112 (EXACT incl. subnormals); scale cancels in n/d.
// MASKS ARE LOAD-BEARING: they strip the other half's bits after the shift.
__device__ __forceinline__ u64 h2f2s(u32 e) {
    u32 lo = (e << 13) & 0x0FFFE000u;
    u32 hi = (e >> 3)  & 0x0FFFE000u;
    return pk2(__uint_as_float(lo), __uint_as_float(hi));
}

__global__ __launch_bounds__(128, 10) void rsca_kernel(
    const float* __restrict__ x, const float* __restrict__ y,
    const float* __restrict__ swq, const float* __restrict__ swk,
    const float* __restrict__ swv, const float* __restrict__ sbq,
    const float* __restrict__ sbk, const float* __restrict__ sbv,
    const float* __restrict__ swo, const float* __restrict__ sbo,
    float* __restrict__ out)
{
    const int n = blockIdx.x;
    const int i = threadIdx.x;

    __shared__ float4 xs[HALF_QUADS];     // 13312 B : 64-row staging window
    __shared__ float4 kv[B_DIM];          // {kx, ky, vx, vy}
    __shared__ float4 wred[4];

    const float wq = *swq, wk = *swk, wv = *swv;
    const float bq = *sbq, bk = *sbk, bv = *sbv;
    const float wo = *swo, bo = *sbo;

    // ---- Pooling in TWO passes of 64 rows (halves smem -> higher occupancy) ----
    const int a = n & 3;
    const size_t baseq = ((size_t)n * HW - a) >> 2;       // float4 offset, exact
    const float4* g4 = (const float4*)x + baseq;

    float sum = 0.f;

    #pragma unroll
    for (int pass = 0; pass < 2; ++pass) {
        // cooperative load of rows [pass*64, pass*64+64)
        #pragma unroll
        for (int t = 0; t < 7; ++t) {
            int idx = i + t * B_DIM;
            if (idx < HALF_QUADS) {
                int r = idx / ROWQ, q = idx - r * ROWQ;
                xs[idx] = g4[(size_t)(r + pass * 64) * ROW_STRIDE_Q4 + q];
            }
        }
        __syncthreads();

        if ((i >> 6) == pass) {
            const int li = i & 63;
            float4 q0 = xs[li * ROWQ + 0];
            float4 q12 = xs[li * ROWQ + 12];
            float s0 = q0.x + q0.y, s1 = q0.z + q0.w, s2 = 0.f, s3 = 0.f;
            #pragma unroll
            for (int t = 1; t < 12; t += 2) {
                float4 u = xs[li * ROWQ + t];
                float4 w = xs[li * ROWQ + t + 1];
                s0 += u.x; s1 += u.y; s2 += u.z; s3 += u.w;
                s0 += w.x; s1 += w.y; s2 += w.z; s3 += w.w;
            }
            sum = (s0 + s1) + (s2 + s3);   // w0..w51 each exactly once
            // valid window = [a, a+48]; remove the 3 invalid of the 52 loaded
            if (a >= 1) sum -= q0.x;  else sum -= q12.y;   // w0  vs w49
            if (a >= 2) sum -= q0.y;  else sum -= q12.z;   // w1  vs w50
            if (a >= 3) sum -= q0.z;  else sum -= q12.w;   // w2  vs w51
        }
        __syncthreads();
    }

    const float ax = sum * (1.0f / 49.0f);
    const float ay = y[(size_t)i * N_DIM + (size_t)n];

    // ---- projections (k pre-scaled by log2 e) ----
    const float L2E = 1.4426950408889634f;
    const float qx = fmaf(ax, wq, bq);
    const float qy = fmaf(ay, wq, bq);
    const float kx = fmaf(ax, wk, bk) * L2E;
    const float ky = fmaf(ay, wk, bk) * L2E;
    const float vx = fmaf(ax, wv, bv);
    const float vy = fmaf(ay, wv, bv);

    kv[i] = make_float4(kx, ky, vx, vy);

    // ---- block min/max of kx, ky (analytic per-row softmax max) ----
    float kxmx = kx, kxmn = kx, kymx = ky, kymn = ky;
    #pragma unroll
    for (int off = 16; off; off >>= 1) {
        kxmx = fmaxf(kxmx, __shfl_xor_sync(0xFFFFFFFFu, kxmx, off));
        kxmn = fminf(kxmn, __shfl_xor_sync(0xFFFFFFFFu, kxmn, off));
        kymx = fmaxf(kymx, __shfl_xor_sync(0xFFFFFFFFu, kymx, off));
        kymn = fminf(kymn, __shfl_xor_sync(0xFFFFFFFFu, kymn, off));
    }
    if ((i & 31) == 0) wred[i >> 5] = make_float4(kxmx, kxmn, kymx, kymn);
    __syncthreads();
    {
        float4 r0 = wred[0], r1 = wred[1], r2 = wred[2], r3 = wred[3];
        kxmx = fmaxf(fmaxf(r0.x, r1.x), fmaxf(r2.x, r3.x));
        kxmn = fminf(fminf(r0.y, r1.y), fminf(r2.y, r3.y));
        kymx = fmaxf(fmaxf(r0.z, r1.z), fmaxf(r2.z, r3.z));
        kymn = fminf(fminf(r0.w, r1.w), fminf(r2.w, r3.w));
    }

    const float nm1 = -((qx >= 0.f) ? qx * kxmx : qx * kxmn);  // self_x : qx,kx
    const float nm2 = -((qy >= 0.f) ? qy * kymx : qy * kymn);  // self_y : qy,ky
    const float nm3 = -((qx >= 0.f) ? qx * kymx : qx * kymn);  // cross_x: qx,ky
    const float nm4 = -((qy >= 0.f) ? qy * kxmx : qy * kxmn);  // cross_y: qy,kx

    const u64 qp12 = pk2(qx, qy);      // lanes (s1, s2)
    const u64 qp43 = pk2(qy, qx);      // lanes (s4, s3)
    const u64 nmp12 = pk2(nm1, nm2);
    const u64 nmp43 = pk2(nm4, nm3);

    // ---- fused 4-combo attention: 2 f16x2 MUFU exps per j (= 4 exps) ----
    u64 d12 = 0, n12 = 0, d43 = 0, n43 = 0;

    #pragma unroll 8
    for (int j = 0; j < B_DIM; ++j) {
        const float4 p = kv[j];            // {kx, ky, vx, vy} (warp-uniform)
        const u64 kp = pk2(p.x, p.y);
        const u64 vp = pk2(p.z, p.w);

        const u64 sc12 = fma2(qp12, kp, nmp12);    // (s1, s2), <= 0
        const u64 sc43 = fma2(qp43, kp, nmp43);    // (s4, s3), <= 0

        const u32 e12 = ex2h2(sc12);               // 1 MUFU: e1, e2
        const u32 e43 = ex2h2(sc43);               // 1 MUFU: e4, e3

        const u64 f12 = h2f2s(e12);                // f32x2, x 2^-112 exact
        const u64 f43 = h2f2s(e43);

        d12 = add2(d12, f12); n12 = fma2(f12, vp, n12);   // n1+=e1*vx, n2+=e2*vy
        d43 = add2(d43, f43); n43 = fma2(f43, vp, n43);   // n4+=e4*vx, n3+=e3*vy
    }

    float nn1, nn2, dd1, dd2, nn4, nn3, dd4, dd3;
    upk2(n12, nn1, nn2); upk2(d12, dd1, dd2);
    upk2(n43, nn4, nn3); upk2(d43, dd4, dd3);

    const float osx = __fdividef(nn1, dd1);   // 2^-112 scale cancels
    const float osy = __fdividef(nn2, dd2);
    const float ocx = __fdividef(nn3, dd3);
    const float ocy = __fdividef(nn4, dd4);

    const float ox = fmaf(wo, osx + ocx, ax + 2.0f * bo);
    const float oy = fmaf(wo, osy + ocy, ay + 2.0f * bo);

    out[(size_t)i * (2 * N_DIM) + (size_t)n]         = ox;
    out[(size_t)i * (2 * N_DIM) + N_DIM + (size_t)n] = oy;
}

extern "C" void kernel_launch(void* const* d_in, const int* in_sizes, int n_in,
                              void* d_out, int out_size) {
    const float* x   = (const float*)d_in[0];
    const float* y   = (const float*)d_in[1];
    const float* swq = (const float*)d_in[2];
    const float* swk = (const float*)d_in[3];
    const float* swv = (const float*)d_in[4];
    const float* sbq = (const float*)d_in[5];
    const float* sbk = (const float*)d_in[6];
    const float* sbv = (const float*)d_in[7];
    const float* swo = (const float*)d_in[8];
    const float* sbo = (const float*)d_in[9];
    float* out = (float*)d_out;

    rsca_kernel<<<N_DIM, B_DIM>>>(x, y, swq, swk, swv, sbq, sbk, sbv, swo, sbo, out);
}

// round 9
// speedup vs baseline: 1.3712x; 1.0161x over previous
#include <cuda_runtime.h>

#define B_DIM 128
#define N_DIM 8192
#define HW    49
#define ROWQ  13               // float4 quads per row window (52 floats)
#define HALF_QUADS (64 * ROWQ) // 832 quads staged per pass
#define ROW_STRIDE_Q4 100352   // 8192*49/4 : float4 stride between rows of x

typedef unsigned long long u64;
typedef unsigned int u32;

__device__ __forceinline__ u64 pk2(float lo, float hi) {
    u64 r; asm("mov.b64 %0, {%1,%2};" : "=l"(r) : "f"(lo), "f"(hi)); return r;
}
__device__ __forceinline__ void upk2(u64 v, float& lo, float& hi) {
    asm("mov.b64 {%0,%1}, %2;" : "=f"(lo), "=f"(hi) : "l"(v));
}
__device__ __forceinline__ u64 fma2(u64 a, u64 b, u64 c) {
    u64 d; asm("fma.rn.f32x2 %0, %1, %2, %3;" : "=l"(d) : "l"(a), "l"(b), "l"(c)); return d;
}
__device__ __forceinline__ u64 add2(u64 a, u64 b) {
    u64 d; asm("add.rn.f32x2 %0, %1, %2;" : "=l"(d) : "l"(a), "l"(b)); return d;
}
// f32x2 arg -> f16x2 -> 2^t for both halves: ONE MUFU instruction for two exps
__device__ __forceinline__ u32 ex2h2(u64 a) {
    float lo, hi; upk2(a, lo, hi);
    u32 h; asm("cvt.rn.f16x2.f32 %0, %1, %2;" : "=r"(h) : "f"(hi), "f"(lo));
    u32 e; asm("ex2.approx.f16x2 %0, %1;" : "=r"(e) : "r"(h));
    return e;
}
// f16x2 -> f32x2 scaled 2^-112 (EXACT incl. subnormals); scale cancels in n/d.
// MASKS ARE LOAD-BEARING. hi-shift done as IMAD.HI (mul.hi.u32) -> fma pipe,
// rebalancing the unpack off the saturated alu pipe. Numerically identical.
__device__ __forceinline__ u64 h2f2s(u32 e) {
    u32 lo = (e << 13) & 0x0FFFE000u;      // alu: SHF + LOP3
    u32 hi;
    asm("mul.hi.u32 %0, %1, %2;" : "=r"(hi) : "r"(e), "r"(0x20000000u)); // fma: IMAD.HI == e>>3
    hi &= 0x0FFFE000u;                     // alu: LOP3
    return pk2(__uint_as_float(lo), __uint_as_float(hi));
}

__global__ __launch_bounds__(128, 10) void rsca_kernel(
    const float* __restrict__ x, const float* __restrict__ y,
    const float* __restrict__ swq, const float* __restrict__ swk,
    const float* __restrict__ swv, const float* __restrict__ sbq,
    const float* __restrict__ sbk, const float* __restrict__ sbv,
    const float* __restrict__ swo, const float* __restrict__ sbo,
    float* __restrict__ out)
{
    const int n = blockIdx.x;
    const int i = threadIdx.x;

    __shared__ float4 xs[HALF_QUADS];     // 13312 B : 64-row staging window
    __shared__ float4 kv[B_DIM];          // {kx, ky, vx, vy}
    __shared__ float4 wred[4];

    const float wq = *swq, wk = *swk, wv = *swv;
    const float bq = *sbq, bk = *sbk, bv = *sbv;
    const float wo = *swo, bo = *sbo;

    // ---- Pooling in TWO passes of 64 rows ----
    const int a = n & 3;
    const size_t baseq = ((size_t)n * HW - a) >> 2;       // float4 offset, exact
    const float4* g4 = (const float4*)x + baseq;

    float sum = 0.f;

    #pragma unroll
    for (int pass = 0; pass < 2; ++pass) {
        #pragma unroll
        for (int t = 0; t < 7; ++t) {
            int idx = i + t * B_DIM;
            if (idx < HALF_QUADS) {
                int r = idx / ROWQ, q = idx - r * ROWQ;
                xs[idx] = g4[(size_t)(r + pass * 64) * ROW_STRIDE_Q4 + q];
            }
        }
        __syncthreads();

        if ((i >> 6) == pass) {
            const int li = i & 63;
            float4 q0 = xs[li * ROWQ + 0];
            float4 q12 = xs[li * ROWQ + 12];
            float s0 = q0.x + q0.y, s1 = q0.z + q0.w, s2 = 0.f, s3 = 0.f;
            #pragma unroll
            for (int t = 1; t < 12; t += 2) {
                float4 u = xs[li * ROWQ + t];
                float4 w = xs[li * ROWQ + t + 1];
                s0 += u.x; s1 += u.y; s2 += u.z; s3 += u.w;
                s0 += w.x; s1 += w.y; s2 += w.z; s3 += w.w;
            }
            sum = (s0 + s1) + (s2 + s3);   // w0..w51 each exactly once
            if (a >= 1) sum -= q0.x;  else sum -= q12.y;   // w0  vs w49
            if (a >= 2) sum -= q0.y;  else sum -= q12.z;   // w1  vs w50
            if (a >= 3) sum -= q0.z;  else sum -= q12.w;   // w2  vs w51
        }
        __syncthreads();
    }

    const float ax = sum * (1.0f / 49.0f);
    const float ay = y[(size_t)i * N_DIM + (size_t)n];

    // ---- projections (k pre-scaled by log2 e) ----
    const float L2E = 1.4426950408889634f;
    const float qx = fmaf(ax, wq, bq);
    const float qy = fmaf(ay, wq, bq);
    const float kx = fmaf(ax, wk, bk) * L2E;
    const float ky = fmaf(ay, wk, bk) * L2E;
    const float vx = fmaf(ax, wv, bv);
    const float vy = fmaf(ay, wv, bv);

    kv[i] = make_float4(kx, ky, vx, vy);

    // ---- block min/max of kx, ky (analytic per-row softmax max) ----
    float kxmx = kx, kxmn = kx, kymx = ky, kymn = ky;
    #pragma unroll
    for (int off = 16; off; off >>= 1) {
        kxmx = fmaxf(kxmx, __shfl_xor_sync(0xFFFFFFFFu, kxmx, off));
        kxmn = fminf(kxmn, __shfl_xor_sync(0xFFFFFFFFu, kxmn, off));
        kymx = fmaxf(kymx, __shfl_xor_sync(0xFFFFFFFFu, kymx, off));
        kymn = fminf(kymn, __shfl_xor_sync(0xFFFFFFFFu, kymn, off));
    }
    if ((i & 31) == 0) wred[i >> 5] = make_float4(kxmx, kxmn, kymx, kymn);
    __syncthreads();
    {
        float4 r0 = wred[0], r1 = wred[1], r2 = wred[2], r3 = wred[3];
        kxmx = fmaxf(fmaxf(r0.x, r1.x), fmaxf(r2.x, r3.x));
        kxmn = fminf(fminf(r0.y, r1.y), fminf(r2.y, r3.y));
        kymx = fmaxf(fmaxf(r0.z, r1.z), fmaxf(r2.z, r3.z));
        kymn = fminf(fminf(r0.w, r1.w), fminf(r2.w, r3.w));
    }

    const float nm1 = -((qx >= 0.f) ? qx * kxmx : qx * kxmn);  // self_x : qx,kx
    const float nm2 = -((qy >= 0.f) ? qy * kymx : qy * kymn);  // self_y : qy,ky
    const float nm3 = -((qx >= 0.f) ? qx * kymx : qx * kymn);  // cross_x: qx,ky
    const float nm4 = -((qy >= 0.f) ? qy * kxmx : qy * kxmn);  // cross_y: qy,kx

    const u64 qp12 = pk2(qx, qy);      // lanes (s1, s2)
    const u64 qp43 = pk2(qy, qx);      // lanes (s4, s3)
    const u64 nmp12 = pk2(nm1, nm2);
    const u64 nmp43 = pk2(nm4, nm3);

    // ---- fused 4-combo attention: 2 f16x2 MUFU exps per j (= 4 exps) ----
    u64 d12 = 0, n12 = 0, d43 = 0, n43 = 0;

    #pragma unroll 16
    for (int j = 0; j < B_DIM; ++j) {
        const float4 p = kv[j];            // {kx, ky, vx, vy} (warp-uniform)
        const u64 kp = pk2(p.x, p.y);
        const u64 vp = pk2(p.z, p.w);

        const u64 sc12 = fma2(qp12, kp, nmp12);    // (s1, s2), <= 0
        const u64 sc43 = fma2(qp43, kp, nmp43);    // (s4, s3), <= 0

        const u32 e12 = ex2h2(sc12);               // 1 MUFU: e1, e2
        const u32 e43 = ex2h2(sc43);               // 1 MUFU: e4, e3

        const u64 f12 = h2f2s(e12);                // f32x2, x 2^-112 exact
        const u64 f43 = h2f2s(e43);

        d12 = add2(d12, f12); n12 = fma2(f12, vp, n12);   // n1+=e1*vx, n2+=e2*vy
        d43 = add2(d43, f43); n43 = fma2(f43, vp, n43);   // n4+=e4*vx, n3+=e3*vy
    }

    float nn1, nn2, dd1, dd2, nn4, nn3, dd4, dd3;
    upk2(n12, nn1, nn2); upk2(d12, dd1, dd2);
    upk2(n43, nn4, nn3); upk2(d43, dd4, dd3);

    const float osx = __fdividef(nn1, dd1);   // 2^-112 scale cancels
    const float osy = __fdividef(nn2, dd2);
    const float ocx = __fdividef(nn3, dd3);
    const float ocy = __fdividef(nn4, dd4);

    const float ox = fmaf(wo, osx + ocx, ax + 2.0f * bo);
    const float oy = fmaf(wo, osy + ocy, ay + 2.0f * bo);

    out[(size_t)i * (2 * N_DIM) + (size_t)n]         = ox;
    out[(size_t)i * (2 * N_DIM) + N_DIM + (size_t)n] = oy;
}

extern "C" void kernel_launch(void* const* d_in, const int* in_sizes, int n_in,
                              void* d_out, int out_size) {
    const float* x   = (const float*)d_in[0];
    const float* y   = (const float*)d_in[1];
    const float* swq = (const float*)d_in[2];
    const float* swk = (const float*)d_in[3];
    const float* swv = (const float*)d_in[4];
    const float* sbq = (const float*)d_in[5];
    const float* sbk = (const float*)d_in[6];
    const float* sbv = (const float*)d_in[7];
    const float* swo = (const float*)d_in[8];
    const float* sbo = (const float*)d_in[9];
    float* out = (float*)d_out;

    rsca_kernel<<<N_DIM, B_DIM>>>(x, y, swq, swk, swv, sbq, sbk, sbv, swo, sbo, out);
}

// round 10
// speedup vs baseline: 1.5410x; 1.1238x over previous
#include <cuda_runtime.h>

#define B_DIM 128
#define N_DIM 8192
#define HW    49
#define ROWQ  13               // float4 quads per row window (52 floats)
#define HALF_QUADS (64 * ROWQ) // 832 quads staged per pass
#define ROW_STRIDE_Q4 100352   // 8192*49/4 : float4 stride between rows of x

typedef unsigned long long u64;
typedef unsigned int u32;

__device__ __forceinline__ u64 pk2(float lo, float hi) {
    u64 r; asm("mov.b64 %0, {%1,%2};" : "=l"(r) : "f"(lo), "f"(hi)); return r;
}
__device__ __forceinline__ void upk2(u64 v, float& lo, float& hi) {
    asm("mov.b64 {%0,%1}, %2;" : "=f"(lo), "=f"(hi) : "l"(v));
}
__device__ __forceinline__ u64 fma2(u64 a, u64 b, u64 c) {
    u64 d; asm("fma.rn.f32x2 %0, %1, %2, %3;" : "=l"(d) : "l"(a), "l"(b), "l"(c)); return d;
}
__device__ __forceinline__ u64 add2(u64 a, u64 b) {
    u64 d; asm("add.rn.f32x2 %0, %1, %2;" : "=l"(d) : "l"(a), "l"(b)); return d;
}
__device__ __forceinline__ float ex2f(float x) {
    float y; asm("ex2.approx.ftz.f32 %0, %1;" : "=f"(y) : "f"(x)); return y;
}
// f32x2 arg -> f16x2 -> 2^t for both halves (1 PTX MUFU op)
__device__ __forceinline__ u32 ex2h2(u64 a) {
    float lo, hi; upk2(a, lo, hi);
    u32 h; asm("cvt.rn.f16x2.f32 %0, %1, %2;" : "=r"(h) : "f"(hi), "f"(lo));
    u32 e; asm("ex2.approx.f16x2 %0, %1;" : "=r"(e) : "r"(h));
    return e;
}
// f16x2 -> f32x2 scaled 2^-112 (EXACT incl. subnormals); scale cancels in n/d.
// MASKS ARE LOAD-BEARING. hi extraction via IMAD.HI keeps it on the fma pipe.
__device__ __forceinline__ u64 h2f2s(u32 e) {
    u32 lo = (e << 13) & 0x0FFFE000u;      // alu: SHF + LOP3
    u32 hi;
    asm("mul.hi.u32 %0, %1, %2;" : "=r"(hi) : "r"(e), "r"(0x20000000u)); // fma: == e>>3
    hi &= 0x0FFFE000u;                     // alu: LOP3
    return pk2(__uint_as_float(lo), __uint_as_float(hi));
}

__global__ __launch_bounds__(128, 12) void rsca_kernel(
    const float* __restrict__ x, const float* __restrict__ y,
    const float* __restrict__ swq, const float* __restrict__ swk,
    const float* __restrict__ swv, const float* __restrict__ sbq,
    const float* __restrict__ sbk, const float* __restrict__ sbv,
    const float* __restrict__ swo, const float* __restrict__ sbo,
    float* __restrict__ out)
{
    const int n = blockIdx.x;
    const int i = threadIdx.x;

    __shared__ float4 xs[HALF_QUADS];     // 13312 B : 64-row staging window
    __shared__ float4 kv[B_DIM];          // {kx, ky, vx, vy}
    __shared__ float4 wred[4];

    const float wq = *swq, wk = *swk, wv = *swv;
    const float bq = *sbq, bk = *sbk, bv = *sbv;
    const float wo = *swo, bo = *sbo;

    // ---- Pooling in TWO passes of 64 rows ----
    const int a = n & 3;
    const size_t baseq = ((size_t)n * HW - a) >> 2;       // float4 offset, exact
    const float4* g4 = (const float4*)x + baseq;

    float sum = 0.f;

    #pragma unroll
    for (int pass = 0; pass < 2; ++pass) {
        #pragma unroll
        for (int t = 0; t < 7; ++t) {
            int idx = i + t * B_DIM;
            if (idx < HALF_QUADS) {
                int r = idx / ROWQ, q = idx - r * ROWQ;
                xs[idx] = g4[(size_t)(r + pass * 64) * ROW_STRIDE_Q4 + q];
            }
        }
        __syncthreads();

        if ((i >> 6) == pass) {
            const int li = i & 63;
            float4 q0 = xs[li * ROWQ + 0];
            float4 q12 = xs[li * ROWQ + 12];
            float s0 = q0.x + q0.y, s1 = q0.z + q0.w, s2 = 0.f, s3 = 0.f;
            #pragma unroll
            for (int t = 1; t < 12; t += 2) {
                float4 u = xs[li * ROWQ + t];
                float4 w = xs[li * ROWQ + t + 1];
                s0 += u.x; s1 += u.y; s2 += u.z; s3 += u.w;
                s0 += w.x; s1 += w.y; s2 += w.z; s3 += w.w;
            }
            sum = (s0 + s1) + (s2 + s3);   // w0..w51 each exactly once
            if (a >= 1) sum -= q0.x;  else sum -= q12.y;   // w0  vs w49
            if (a >= 2) sum -= q0.y;  else sum -= q12.z;   // w1  vs w50
            if (a >= 3) sum -= q0.z;  else sum -= q12.w;   // w2  vs w51
        }
        __syncthreads();
    }

    const float ax = sum * (1.0f / 49.0f);
    const float ay = y[(size_t)i * N_DIM + (size_t)n];

    // ---- projections (k pre-scaled by log2 e) ----
    const float L2E = 1.4426950408889634f;
    const float qx = fmaf(ax, wq, bq);
    const float qy = fmaf(ay, wq, bq);
    const float kx = fmaf(ax, wk, bk) * L2E;
    const float ky = fmaf(ay, wk, bk) * L2E;
    const float vx = fmaf(ax, wv, bv);
    const float vy = fmaf(ay, wv, bv);

    kv[i] = make_float4(kx, ky, vx, vy);

    // ---- block min/max of kx, ky (analytic per-row softmax max) ----
    float kxmx = kx, kxmn = kx, kymx = ky, kymn = ky;
    #pragma unroll
    for (int off = 16; off; off >>= 1) {
        kxmx = fmaxf(kxmx, __shfl_xor_sync(0xFFFFFFFFu, kxmx, off));
        kxmn = fminf(kxmn, __shfl_xor_sync(0xFFFFFFFFu, kxmn, off));
        kymx = fmaxf(kymx, __shfl_xor_sync(0xFFFFFFFFu, kymx, off));
        kymn = fminf(kymn, __shfl_xor_sync(0xFFFFFFFFu, kymn, off));
    }
    if ((i & 31) == 0) wred[i >> 5] = make_float4(kxmx, kxmn, kymx, kymn);
    __syncthreads();
    {
        float4 r0 = wred[0], r1 = wred[1], r2 = wred[2], r3 = wred[3];
        kxmx = fmaxf(fmaxf(r0.x, r1.x), fmaxf(r2.x, r3.x));
        kxmn = fminf(fminf(r0.y, r1.y), fminf(r2.y, r3.y));
        kymx = fmaxf(fmaxf(r0.z, r1.z), fmaxf(r2.z, r3.z));
        kymn = fminf(fminf(r0.w, r1.w), fminf(r2.w, r3.w));
    }

    const float nm1 = -((qx >= 0.f) ? qx * kxmx : qx * kxmn);  // self_x : qx,kx
    const float nm2 = -((qy >= 0.f) ? qy * kymx : qy * kymn);  // self_y : qy,ky
    const float nm3 = -((qx >= 0.f) ? qx * kymx : qx * kymn);  // cross_x: qx,ky
    const float nm4 = -((qy >= 0.f) ? qy * kxmx : qy * kxmn);  // cross_y: qy,kx

    const u64 qp12 = pk2(qx, qy);      // lanes (s1, s2)
    const u64 qp43 = pk2(qy, qx);      // lanes (s4, s3)
    const u64 nmp12 = pk2(nm1, nm2);
    const u64 nmp43 = pk2(nm4, nm3);

    // ---- fused 4-combo attention: combos 1,2 exact f32 MUFU; combos 4,3 f16x2 ----
    u64 d12 = 0, n12 = 0, d43 = 0, n43 = 0;
    const ulonglong2* kvp = (const ulonglong2*)kv;   // .x = {kx,ky} bits, .y = {vx,vy}

    #pragma unroll 8
    for (int j = 0; j < B_DIM; ++j) {
        const ulonglong2 pv = kvp[j];              // LDS.128 -> two u64 register pairs

        const u64 sc12 = fma2(qp12, pv.x, nmp12);  // (s1, s2), <= 0
        const u64 sc43 = fma2(qp43, pv.x, nmp43);  // (s4, s3), <= 0

        // combos 1,2: exact scalar f32 MUFU
        float t1, t2; upk2(sc12, t1, t2);
        const float e1 = ex2f(t1);
        const float e2 = ex2f(t2);
        const u64 f12 = pk2(e1, e2);

        // combos 4,3: one f16x2 MUFU + exact scaled unpack
        const u32 e43 = ex2h2(sc43);
        const u64 f43 = h2f2s(e43);                // x 2^-112, cancels in n/d

        d12 = add2(d12, f12); n12 = fma2(f12, pv.y, n12);   // n1+=e1*vx, n2+=e2*vy
        d43 = add2(d43, f43); n43 = fma2(f43, pv.y, n43);   // n4+=e4*vx, n3+=e3*vy
    }

    float nn1, nn2, dd1, dd2, nn4, nn3, dd4, dd3;
    upk2(n12, nn1, nn2); upk2(d12, dd1, dd2);
    upk2(n43, nn4, nn3); upk2(d43, dd4, dd3);

    const float osx = __fdividef(nn1, dd1);
    const float osy = __fdividef(nn2, dd2);
    const float ocx = __fdividef(nn3, dd3);   // 2^-112 scale cancels
    const float ocy = __fdividef(nn4, dd4);

    const float ox = fmaf(wo, osx + ocx, ax + 2.0f * bo);
    const float oy = fmaf(wo, osy + ocy, ay + 2.0f * bo);

    out[(size_t)i * (2 * N_DIM) + (size_t)n]         = ox;
    out[(size_t)i * (2 * N_DIM) + N_DIM + (size_t)n] = oy;
}

extern "C" void kernel_launch(void* const* d_in, const int* in_sizes, int n_in,
                              void* d_out, int out_size) {
    const float* x   = (const float*)d_in[0];
    const float* y   = (const float*)d_in[1];
    const float* swq = (const float*)d_in[2];
    const float* swk = (const float*)d_in[3];
    const float* swv = (const float*)d_in[4];
    const float* sbq = (const float*)d_in[5];
    const float* sbk = (const float*)d_in[6];
    const float* sbv = (const float*)d_in[7];
    const float* swo = (const float*)d_in[8];
    const float* sbo = (const float*)d_in[9];
    float* out = (float*)d_out;

    rsca_kernel<<<N_DIM, B_DIM>>>(x, y, swq, swk, swv, sbq, sbk, sbv, swo, sbo, out);
}